// round 1
// baseline (speedup 1.0000x reference)
#include <cuda_runtime.h>
#include <cuda_bf16.h>
#include <cstdint>

// Problem constants (ISNELayer: N=100000 nodes, H=128, E=625000 edges)
#define MAX_N 100000
#define MAX_E 625000
#define H 128
#define H4 (H / 4)   // 32 float4 per row

// Scratch (no cudaMalloc allowed)
__device__ int   g_counts[MAX_N];
__device__ float g_inv[MAX_N];

// ---------------------------------------------------------------------------
// Kernel 1: zero counts
__global__ void k_zero_counts(int n) {
    int i = blockIdx.x * blockDim.x + threadIdx.x;
    if (i < n) g_counts[i] = 0;
}

// ---------------------------------------------------------------------------
// Kernel 2: per-target edge counts
__global__ void k_count(const int* __restrict__ tgt, int e) {
    int i = blockIdx.x * blockDim.x + threadIdx.x;
    if (i < e) {
        atomicAdd(&g_counts[tgt[i]], 1);
    }
}

// ---------------------------------------------------------------------------
// Kernel 3: inv = 1/max(count,1), and zero the output (it is poisoned 0xAA)
__global__ void k_prep(float4* __restrict__ out, int n) {
    int i = blockIdx.x * blockDim.x + threadIdx.x;
    if (i < n) {
        int c = g_counts[i];
        g_inv[i] = 1.0f / (float)(c > 1 ? c : 1);
    }
    int total4 = n * H4;
    int stride = gridDim.x * blockDim.x;
    float4 z = make_float4(0.f, 0.f, 0.f, 0.f);
    for (int j = i; j < total4; j += stride) {
        out[j] = z;
    }
}

// ---------------------------------------------------------------------------
// Kernel 4: scatter. One warp per edge; lane l handles float4 at column 4*l.
// Pre-scaled by 1/count so no divide pass is needed afterwards.
__global__ void k_scatter(const int* __restrict__ node_ids,
                          const int* __restrict__ e_src,
                          const int* __restrict__ e_tgt,
                          const float4* __restrict__ emb,
                          float4* __restrict__ out,
                          int e) {
    int gtid = blockIdx.x * blockDim.x + threadIdx.x;
    int warp = gtid >> 5;
    int lane = threadIdx.x & 31;
    if (warp >= e) return;

    int src_idx = e_src[warp];           // broadcast load (uniform per warp)
    int tgt     = e_tgt[warp];
    int src     = node_ids[src_idx];     // identity in practice, but honor the gather
    float inv   = g_inv[tgt];

    float4 v = emb[(long)src * H4 + lane];   // LDG.128, coalesced across warp
    v.x *= inv; v.y *= inv; v.z *= inv; v.w *= inv;

    float4* p = out + (long)tgt * H4 + lane;
    // Vector f32 reduction (sm_90+): single REDG of 16B, no return value.
    asm volatile("red.global.add.v4.f32 [%0], {%1, %2, %3, %4};"
                 :: "l"(p), "f"(v.x), "f"(v.y), "f"(v.z), "f"(v.w)
                 : "memory");
}

// ---------------------------------------------------------------------------
extern "C" void kernel_launch(void* const* d_in, const int* in_sizes, int n_in,
                              void* d_out, int out_size) {
    const int*   node_ids = (const int*)d_in[0];                 // [N] int32
    const int*   edge     = (const int*)d_in[1];                 // [2, E] int32
    const float* emb      = (const float*)d_in[2];               // [N, H] fp32
    float*       out      = (float*)d_out;                       // [N, H] fp32

    int n = in_sizes[0];
    int e = in_sizes[1] / 2;
    if (n > MAX_N) n = MAX_N;
    if (e > MAX_E) e = MAX_E;

    const int* e_src = edge;       // edge_index[0]
    const int* e_tgt = edge + e;   // edge_index[1]

    const int T = 256;

    // 1. zero counts
    k_zero_counts<<<(n + T - 1) / T, T>>>(n);

    // 2. count edges per target
    k_count<<<(e + T - 1) / T, T>>>(e_tgt, e);

    // 3. inv + zero output
    {
        int total4 = n * H4;
        int blocks = (total4 + T - 1) / T;   // covers both loops (total4 >= n)
        k_prep<<<blocks, T>>>((float4*)out, n);
    }

    // 4. scatter (one warp per edge)
    {
        long threads = (long)e * 32;
        int blocks = (int)((threads + T - 1) / T);
        k_scatter<<<blocks, T>>>(node_ids, e_src, e_tgt,
                                 (const float4*)emb, (float4*)out, e);
    }
}

// round 2
// speedup vs baseline: 1.6050x; 1.6050x over previous
#include <cuda_runtime.h>
#include <cuda_bf16.h>
#include <cstdint>

// Problem constants (ISNELayer: N=100000 nodes, H=128, E=625000 edges)
#define MAX_N 100000
#define MAX_E 625000
#define H 128
#define H4 (H / 4)        // 32 float4 per row (1 float4 per lane)
#define BCAP 64           // bucket capacity per node (Poisson(6.25): overflow ~impossible)
#define OVF_CAP 65536

// Scratch (static device arrays; no cudaMalloc allowed)
__device__ int g_counts[MAX_N];
__device__ int g_bucket[(size_t)MAX_N * BCAP];   // 25.6 MB
__device__ int g_ovf_cnt;
__device__ int g_ovf_src[OVF_CAP];
__device__ int g_ovf_tgt[OVF_CAP];

// ---------------------------------------------------------------------------
// Kernel 1: zero counts + overflow cursor
__global__ void k_zero(int n) {
    int i = blockIdx.x * blockDim.x + threadIdx.x;
    if (i < n) g_counts[i] = 0;
    if (i == 0) g_ovf_cnt = 0;
}

// ---------------------------------------------------------------------------
// Kernel 2: fill buckets — one thread per edge.
// Resolves the node_ids gather here so buckets store final row indices.
__global__ void k_fill(const int* __restrict__ node_ids,
                       const int* __restrict__ e_src,
                       const int* __restrict__ e_tgt,
                       int e) {
    int i = blockIdx.x * blockDim.x + threadIdx.x;
    if (i >= e) return;
    int t   = e_tgt[i];
    int src = node_ids[e_src[i]];
    int pos = atomicAdd(&g_counts[t], 1);
    if (pos < BCAP) {
        g_bucket[(size_t)t * BCAP + pos] = src;
    } else {
        int oi = atomicAdd(&g_ovf_cnt, 1);
        if (oi < OVF_CAP) { g_ovf_src[oi] = src; g_ovf_tgt[oi] = t; }
    }
}

// ---------------------------------------------------------------------------
// Kernel 3: gather-accumulate — one warp per target node.
// Lane l owns float4 column 4*l. Source rows issued as independent LDG.128s.
__global__ void k_gather(const float4* __restrict__ emb,
                         float4* __restrict__ out,
                         int n) {
    int gtid = blockIdx.x * blockDim.x + threadIdx.x;
    int warp = gtid >> 5;
    int lane = threadIdx.x & 31;
    if (warp >= n) return;

    int t       = warp;
    int deg_all = g_counts[t];
    int deg     = deg_all < BCAP ? deg_all : BCAP;

    float4 acc = make_float4(0.f, 0.f, 0.f, 0.f);
    const int* bk = g_bucket + (size_t)t * BCAP;

    for (int j0 = 0; j0 < deg; j0 += 32) {
        int rem = deg - j0;                 // 1..32 this batch
        int cnt = rem < 32 ? rem : 32;
        int my_src = (lane < cnt) ? bk[j0 + lane] : 0;
        #pragma unroll 8
        for (int k = 0; k < cnt; k++) {
            int s = __shfl_sync(0xFFFFFFFFu, my_src, k);
            float4 v = __ldg(&emb[(size_t)s * H4 + lane]);
            acc.x += v.x; acc.y += v.y; acc.z += v.z; acc.w += v.w;
        }
    }

    float inv = 1.0f / (float)(deg_all > 1 ? deg_all : 1);
    acc.x *= inv; acc.y *= inv; acc.z *= inv; acc.w *= inv;
    out[(size_t)t * H4 + lane] = acc;
}

// ---------------------------------------------------------------------------
// Kernel 4: overflow cleanup (practically empty). One warp per overflow edge,
// grid-stride; adds the pre-scaled row via vector reduction.
__global__ void k_overflow(const float4* __restrict__ emb,
                           float4* __restrict__ out) {
    int nwarps = (gridDim.x * blockDim.x) >> 5;
    int warp   = (blockIdx.x * blockDim.x + threadIdx.x) >> 5;
    int lane   = threadIdx.x & 31;
    int cnt    = g_ovf_cnt;
    if (cnt > OVF_CAP) cnt = OVF_CAP;
    for (int i = warp; i < cnt; i += nwarps) {
        int s = g_ovf_src[i];
        int t = g_ovf_tgt[i];
        int d = g_counts[t];
        float inv = 1.0f / (float)(d > 1 ? d : 1);
        float4 v = emb[(size_t)s * H4 + lane];
        v.x *= inv; v.y *= inv; v.z *= inv; v.w *= inv;
        float4* p = out + (size_t)t * H4 + lane;
        asm volatile("red.global.add.v4.f32 [%0], {%1, %2, %3, %4};"
                     :: "l"(p), "f"(v.x), "f"(v.y), "f"(v.z), "f"(v.w)
                     : "memory");
    }
}

// ---------------------------------------------------------------------------
extern "C" void kernel_launch(void* const* d_in, const int* in_sizes, int n_in,
                              void* d_out, int out_size) {
    const int*   node_ids = (const int*)d_in[0];   // [N] int32
    const int*   edge     = (const int*)d_in[1];   // [2, E] int32
    const float* emb      = (const float*)d_in[2]; // [N, H] fp32
    float*       out      = (float*)d_out;         // [N, H] fp32

    int n = in_sizes[0];
    int e = in_sizes[1] / 2;
    if (n > MAX_N) n = MAX_N;
    if (e > MAX_E) e = MAX_E;

    const int* e_src = edge;       // edge_index[0]
    const int* e_tgt = edge + e;   // edge_index[1]

    const int T = 256;

    k_zero<<<(n + T - 1) / T, T>>>(n);
    k_fill<<<(e + T - 1) / T, T>>>(node_ids, e_src, e_tgt, e);

    {
        long threads = (long)n * 32;               // one warp per node
        int blocks = (int)((threads + T - 1) / T);
        k_gather<<<blocks, T>>>((const float4*)emb, (float4*)out, n);
    }

    k_overflow<<<64, T>>>((const float4*)emb, (float4*)out);
}

// round 3
// speedup vs baseline: 1.7549x; 1.0934x over previous
#include <cuda_runtime.h>
#include <cuda_bf16.h>
#include <cstdint>

// Problem constants (ISNELayer: N=100000 nodes, H=128, E=625000 edges)
#define MAX_N 100000
#define MAX_E 625000
#define H 128
#define H4 (H / 4)        // 32 float4 per row (1 float4 per lane)
#define BCAP 32           // bucket capacity per node; P(Poisson(6.25) > 32) ~ 1e-18
#define OVF_CAP 65536

// Scratch (static device arrays; no cudaMalloc allowed)
// g_counts[0..MAX_N-1] = per-target degree; g_counts[MAX_N] = overflow cursor.
__device__ int g_counts[MAX_N + 1];
__device__ int g_bucket[(size_t)MAX_N * BCAP];   // 12.8 MB
__device__ int g_ovf_src[OVF_CAP];
__device__ int g_ovf_tgt[OVF_CAP];

// ---------------------------------------------------------------------------
// Kernel 1: fill buckets — one thread per edge.
// Resolves the node_ids gather here so buckets store final row indices.
__global__ void k_fill(const int* __restrict__ node_ids,
                       const int* __restrict__ e_src,
                       const int* __restrict__ e_tgt,
                       int e) {
    int i = blockIdx.x * blockDim.x + threadIdx.x;
    if (i >= e) return;
    int t   = e_tgt[i];
    int src = node_ids[e_src[i]];
    int pos = atomicAdd(&g_counts[t], 1);
    if (pos < BCAP) {
        g_bucket[(size_t)t * BCAP + pos] = src;
    } else {
        int oi = atomicAdd(&g_counts[MAX_N], 1);
        if (oi < OVF_CAP) { g_ovf_src[oi] = src; g_ovf_tgt[oi] = t; }
    }
}

// ---------------------------------------------------------------------------
// Kernel 2: gather-accumulate — one warp per target node.
// Lane l owns float4 column 4*l. Source rows issued as independent LDG.128s.
// Overflow fixup (practically never taken) is folded in at the end.
__global__ void k_gather(const float4* __restrict__ emb,
                         float4* __restrict__ out,
                         int n) {
    int gtid = blockIdx.x * blockDim.x + threadIdx.x;
    int warp = gtid >> 5;
    int lane = threadIdx.x & 31;
    if (warp >= n) return;

    int t       = warp;
    int deg_all = g_counts[t];
    int deg     = deg_all < BCAP ? deg_all : BCAP;

    float4 acc = make_float4(0.f, 0.f, 0.f, 0.f);
    const int* bk = g_bucket + (size_t)t * BCAP;

    // Single batch: lane j holds source index j (deg <= 32 in practice).
    int my_src = (lane < deg) ? bk[lane] : 0;
    #pragma unroll 8
    for (int k = 0; k < deg; k++) {
        int s = __shfl_sync(0xFFFFFFFFu, my_src, k);
        float4 v = __ldg(&emb[(size_t)s * H4 + lane]);
        acc.x += v.x; acc.y += v.y; acc.z += v.z; acc.w += v.w;
    }

    // Overflow path: only taken if some node exceeded BCAP (cnt is 0 in
    // practice; one broadcast L2 read per warp).
    if (deg_all > BCAP) {
        int cnt = g_counts[MAX_N];
        if (cnt > OVF_CAP) cnt = OVF_CAP;
        for (int i = 0; i < cnt; i++) {
            if (g_ovf_tgt[i] == t) {
                int s = g_ovf_src[i];
                float4 v = __ldg(&emb[(size_t)s * H4 + lane]);
                acc.x += v.x; acc.y += v.y; acc.z += v.z; acc.w += v.w;
            }
        }
    }

    float inv = 1.0f / (float)(deg_all > 1 ? deg_all : 1);
    acc.x *= inv; acc.y *= inv; acc.z *= inv; acc.w *= inv;
    out[(size_t)t * H4 + lane] = acc;
}

// ---------------------------------------------------------------------------
extern "C" void kernel_launch(void* const* d_in, const int* in_sizes, int n_in,
                              void* d_out, int out_size) {
    const int*   node_ids = (const int*)d_in[0];   // [N] int32
    const int*   edge     = (const int*)d_in[1];   // [2, E] int32
    const float* emb      = (const float*)d_in[2]; // [N, H] fp32
    float*       out      = (float*)d_out;         // [N, H] fp32

    int n = in_sizes[0];
    int e = in_sizes[1] / 2;
    if (n > MAX_N) n = MAX_N;
    if (e > MAX_E) e = MAX_E;

    const int* e_src = edge;       // edge_index[0]
    const int* e_tgt = edge + e;   // edge_index[1]

    const int T = 256;

    // Zero counts + overflow cursor via a single memset node (cheaper than a
    // kernel launch; graph-capturable).
    void* counts_ptr = nullptr;
    cudaGetSymbolAddress(&counts_ptr, g_counts);
    cudaMemsetAsync(counts_ptr, 0, (size_t)(MAX_N + 1) * sizeof(int));

    k_fill<<<(e + T - 1) / T, T>>>(node_ids, e_src, e_tgt, e);

    {
        long threads = (long)n * 32;               // one warp per node
        int blocks = (int)((threads + T - 1) / T);
        k_gather<<<blocks, T>>>((const float4*)emb, (float4*)out, n);
    }
}